// round 1
// baseline (speedup 1.0000x reference)
#include <cuda_runtime.h>
#include <cuda_bf16.h>
#include <math.h>

// ---------------- problem constants ----------------
#define NQ      512        // batch (queries)
#define DIM     256        // feature dim
#define KQ      65536      // queue size
#define KNN     200
#define NCLS    1000
#define INVT    (1.0f/0.07f)

#define NF      (KQ*DIM)   // 16,777,216 feature elems
#define NL      KQ         // labels

// out layout (float32): [0]=acc, [1 .. 1+NF)=queue feats, [1+NF .. 1+NF+NL)=labels, [1+NF+NL]=ptr
#define OUT_FEAT_OFF 1
#define OUT_LAB_OFF  (1 + NF)
#define OUT_PTR_OFF  (1 + NF + NL)

// ---------------- device scratch ----------------
__device__ float g_sim[(size_t)NQ * KQ];   // 128 MB scratch for similarity matrix
__device__ int   g_correct;

// ---------------- helpers ----------------
__device__ __forceinline__ unsigned orderf(float f) {
    unsigned u = __float_as_uint(f);
    return (u & 0x80000000u) ? ~u : (u | 0x80000000u);
}

// ---------------- kernel 0: zero counters ----------------
__global__ void zero_kernel() { g_correct = 0; }

// ---------------- kernel 1: GEMM  C[512,65536] = A[512,256] * B[65536,256]^T ----------------
#define BM 128
#define BN 128
#define BK 16
__global__ void __launch_bounds__(256, 2)
gemm_kernel(const float* __restrict__ A, const float* __restrict__ B) {
    __shared__ float A_s[BK][BM];
    __shared__ float B_s[BK][BN];

    const int tid = threadIdx.x;
    const int bx = blockIdx.x;      // 0..511  (N tiles)
    const int by = blockIdx.y;      // 0..3    (M tiles)
    const int tr = tid >> 4;        // 0..15
    const int tc = tid & 15;        // 0..15

    const float4* A4 = (const float4*)A;   // row stride 64 float4
    const float4* B4 = (const float4*)B;   // row stride 64 float4

    float acc[8][8];
    #pragma unroll
    for (int i = 0; i < 8; i++)
        #pragma unroll
        for (int j = 0; j < 8; j++) acc[i][j] = 0.f;

    for (int kt = 0; kt < DIM / BK; ++kt) {
        // cooperative loads: 128 rows x 4 float4 per tile = 512 float4 each
        #pragma unroll
        for (int i = 0; i < 2; i++) {
            int idx = tid * 2 + i;        // 0..511
            int r   = idx >> 2;           // 0..127
            int c4  = idx & 3;            // 0..3
            float4 va = A4[(size_t)(by * BM + r) * (DIM/4) + kt * 4 + c4];
            A_s[c4*4+0][r] = va.x; A_s[c4*4+1][r] = va.y;
            A_s[c4*4+2][r] = va.z; A_s[c4*4+3][r] = va.w;
            float4 vb = B4[(size_t)(bx * BN + r) * (DIM/4) + kt * 4 + c4];
            B_s[c4*4+0][r] = vb.x; B_s[c4*4+1][r] = vb.y;
            B_s[c4*4+2][r] = vb.z; B_s[c4*4+3][r] = vb.w;
        }
        __syncthreads();

        #pragma unroll
        for (int kk = 0; kk < BK; kk++) {
            float4 a0 = *(const float4*)&A_s[kk][tr * 8];
            float4 a1 = *(const float4*)&A_s[kk][tr * 8 + 4];
            float4 b0 = *(const float4*)&B_s[kk][tc * 8];
            float4 b1 = *(const float4*)&B_s[kk][tc * 8 + 4];
            float a[8] = {a0.x, a0.y, a0.z, a0.w, a1.x, a1.y, a1.z, a1.w};
            float b[8] = {b0.x, b0.y, b0.z, b0.w, b1.x, b1.y, b1.z, b1.w};
            #pragma unroll
            for (int i = 0; i < 8; i++)
                #pragma unroll
                for (int j = 0; j < 8; j++)
                    acc[i][j] = fmaf(a[i], b[j], acc[i][j]);
        }
        __syncthreads();
    }

    const size_t colBase = (size_t)bx * BN + tc * 8;
    #pragma unroll
    for (int i = 0; i < 8; i++) {
        size_t row = (size_t)by * BM + tr * 8 + i;
        float* cp = g_sim + row * KQ + colBase;
        *(float4*)cp       = make_float4(acc[i][0], acc[i][1], acc[i][2], acc[i][3]);
        *(float4*)(cp + 4) = make_float4(acc[i][4], acc[i][5], acc[i][6], acc[i][7]);
    }
}

// ---------------- kernel 2: per-query top-200 select + weighted vote + argmax ----------------
#define NBINS    16384
#define CAND_MAX 1024
#define TOPK_SMEM (NBINS*4 + 1024*4 + CAND_MAX*4 + CAND_MAX*4)

__global__ void __launch_bounds__(256)
topk_kernel(const int* __restrict__ qlabels, const int* __restrict__ labels) {
    extern __shared__ char smem[];
    unsigned* hist   = (unsigned*)smem;                       // NBINS
    float*    scores = (float*)(smem + NBINS * 4);            // 1024 (use 1000)
    float*    cval   = scores + 1024;                         // CAND_MAX
    int*      clab   = (int*)(cval + CAND_MAX);               // CAND_MAX

    __shared__ unsigned s_gsum[256];
    __shared__ int s_B, s_cGreater, s_cnt;
    __shared__ float s_bv[256];
    __shared__ int   s_bi[256];

    const int tid = threadIdx.x;
    const int q   = blockIdx.x;
    const float* row = g_sim + (size_t)q * KQ;

    for (int i = tid; i < NBINS; i += 256) hist[i] = 0u;
    for (int i = tid; i < 1024;  i += 256) scores[i] = 0.f;
    if (tid == 0) s_cnt = 0;
    __syncthreads();

    // pass 1: histogram of order-encoded sims
    for (int i = tid; i < KQ; i += 256) {
        unsigned u = orderf(row[i]);
        atomicAdd(&hist[u >> 18], 1u);
    }
    __syncthreads();

    // group sums (64 bins per group) then serial top-down scan (~320 iters)
    unsigned gs = 0;
    #pragma unroll 8
    for (int b = 0; b < 64; b++) gs += hist[tid * 64 + b];
    s_gsum[tid] = gs;
    __syncthreads();

    if (tid == 0) {
        unsigned cum = 0; int B = 0; unsigned cG = 0;
        for (int g = 255; g >= 0; --g) {
            if (cum + s_gsum[g] >= KNN) {
                for (int b = g * 64 + 63; b >= g * 64; --b) {
                    if (cum + hist[b] >= KNN) { B = b; cG = cum; break; }
                    cum += hist[b];
                }
                break;
            }
            cum += s_gsum[g];
        }
        s_B = B; s_cGreater = (int)cG;
    }
    __syncthreads();

    const int B = s_B;
    int need = KNN - s_cGreater;

    // pass 2: accept strictly-above-boundary; buffer boundary-bin candidates
    for (int i = tid; i < KQ; i += 256) {
        float v = row[i];
        int bin = (int)(orderf(v) >> 18);
        if (bin > B) {
            atomicAdd(&scores[qlabels[i]], expf(v * INVT));
        } else if (bin == B) {
            int p = atomicAdd(&s_cnt, 1);
            if (p < CAND_MAX) { cval[p] = v; clab[p] = qlabels[i]; }
        }
    }
    __syncthreads();

    int cnt = min(s_cnt, CAND_MAX);
    if (need > cnt) need = cnt;

    // rank-select the remaining `need` from boundary candidates (tiny set)
    for (int i = tid; i < cnt; i += 256) {
        float v = cval[i];
        int rank = 0;
        for (int j = 0; j < cnt; j++) {
            float w = cval[j];
            rank += (w > v) || (w == v && j < i);
        }
        if (rank < need) atomicAdd(&scores[clab[i]], expf(v * INVT));
    }
    __syncthreads();

    // argmax over 1000 classes, first-max tie-break (match jnp.argmax)
    float best = -1.f; int bi = NCLS;
    for (int c = tid; c < NCLS; c += 256) {
        float v = scores[c];
        if (v > best) { best = v; bi = c; }   // strided ascending -> smallest idx kept on ties
    }
    s_bv[tid] = best; s_bi[tid] = bi;
    __syncthreads();
    for (int s = 128; s > 0; s >>= 1) {
        if (tid < s) {
            float ov = s_bv[tid + s]; int oi = s_bi[tid + s];
            if (ov > s_bv[tid] || (ov == s_bv[tid] && oi < s_bi[tid])) {
                s_bv[tid] = ov; s_bi[tid] = oi;
            }
        }
        __syncthreads();
    }
    if (tid == 0 && s_bi[0] == labels[q]) atomicAdd(&g_correct, 1);
}

// ---------------- kernel 3: queue update copy (DRAM-bound) ----------------
__global__ void __launch_bounds__(256)
copy_kernel(const float* __restrict__ feats, const int* __restrict__ labels,
            const float* __restrict__ qf, const int* __restrict__ ql,
            const int* __restrict__ qptr, float* __restrict__ out) {
    const int ptr = qptr[0];
    size_t idx = (size_t)blockIdx.x * 256 + threadIdx.x;
    if (idx < (size_t)NF) {
        int r = (int)(idx >> 8);
        int c = (int)(idx & 255);
        int rel = r - ptr; if (rel < 0) rel += KQ;
        float v = (rel < NQ) ? feats[rel * DIM + c] : qf[idx];
        out[OUT_FEAT_OFF + idx] = v;
    } else if (idx < (size_t)NF + NL) {
        int i = (int)(idx - NF);
        int rel = i - ptr; if (rel < 0) rel += KQ;
        out[OUT_LAB_OFF + i] = (float)((rel < NQ) ? labels[rel] : ql[i]);
    }
}

// ---------------- kernel 4: finalize scalars ----------------
__global__ void finalize_kernel(const int* __restrict__ qptr, float* __restrict__ out) {
    out[0] = (float)g_correct * (1.0f / (float)NQ);
    out[OUT_PTR_OFF] = (float)((qptr[0] + NQ) % KQ);
}

// ---------------- launch ----------------
extern "C" void kernel_launch(void* const* d_in, const int* in_sizes, int n_in,
                              void* d_out, int out_size) {
    const float* feats  = (const float*)d_in[0];
    const int*   labels = (const int*)d_in[1];
    const float* qf     = (const float*)d_in[2];
    const int*   ql     = (const int*)d_in[3];
    const int*   qptr   = (const int*)d_in[4];
    float* out = (float*)d_out;

    cudaFuncSetAttribute(topk_kernel, cudaFuncAttributeMaxDynamicSharedMemorySize, TOPK_SMEM);

    zero_kernel<<<1, 1>>>();
    gemm_kernel<<<dim3(KQ / BN, NQ / BM), 256>>>(feats, qf);
    topk_kernel<<<NQ, 256, TOPK_SMEM>>>(ql, labels);

    int total = NF + NL;
    copy_kernel<<<(total + 255) / 256, 256>>>(feats, labels, qf, ql, qptr, out);
    finalize_kernel<<<1, 1>>>(qptr, out);
    (void)in_sizes; (void)n_in; (void)out_size;
}

// round 3
// speedup vs baseline: 1.6170x; 1.6170x over previous
#include <cuda_runtime.h>
#include <cuda_bf16.h>
#include <math.h>
#include <cstdint>

// ---------------- problem constants ----------------
#define NQ      512
#define DIM     256
#define KQ      65536
#define KNN     200
#define NCLS    1000
#define INVT    (1.0f/0.07f)

#define NF      (KQ*DIM)
#define NL      KQ

#define OUT_FEAT_OFF 1
#define OUT_LAB_OFF  (1 + NF)
#define OUT_PTR_OFF  (1 + NF + NL)

// ---------------- device scratch ----------------
__device__ float g_sim[(size_t)NQ * KQ];
__device__ int   g_correct;

__device__ __forceinline__ unsigned orderf(float f) {
    unsigned u = __float_as_uint(f);
    return (u & 0x80000000u) ? ~u : (u | 0x80000000u);
}

// ---------------- kernel 0 ----------------
__global__ void zero_kernel() { g_correct = 0; }

// ---------------- kernel 1: HMMA (mma.sync bf16) GEMM with 3-term split ----------------
// C[512,65536] = A[512,256] * B[65536,256]^T  into g_sim
#define TM 128
#define TN 128
#define KC 32                 // fp32 k-columns per chunk
#define NCHUNK (DIM / KC)     // 8

// smem: 2 buffers x 4 tiles (Ahi, Alo, Bhi, Blo), each [2 k16][128 rows][8 u32]
#define TILE_WORDS (2 * 128 * 8)        // 2048 words = 8KB
#define BUF_WORDS  (4 * TILE_WORDS)     // 32KB
#define GEMM_SMEM  (2 * BUF_WORDS * 4)  // 64KB

__device__ __forceinline__ void mma16816(float* c, const uint32_t* a, const uint32_t* b) {
    asm volatile(
        "mma.sync.aligned.m16n8k16.row.col.f32.bf16.bf16.f32 "
        "{%0,%1,%2,%3}, {%4,%5,%6,%7}, {%8,%9}, {%0,%1,%2,%3};"
        : "+f"(c[0]), "+f"(c[1]), "+f"(c[2]), "+f"(c[3])
        : "r"(a[0]), "r"(a[1]), "r"(a[2]), "r"(a[3]), "r"(b[0]), "r"(b[1]));
}

__global__ void __launch_bounds__(256, 1)
gemm_tc_kernel(const float* __restrict__ A, const float* __restrict__ B) {
    extern __shared__ uint32_t smw[];
    const int tid  = threadIdx.x;
    const int lane = tid & 31;
    const int wid  = tid >> 5;
    const int gID  = lane >> 2;    // 0..7
    const int tig  = lane & 3;     // 0..3
    const int wm   = wid >> 2;     // 0..1
    const int wn   = wid & 3;      // 0..3
    const int tileM = blockIdx.x * TM;   // M fast (4) -> B tile shared via L2
    const int tileN = blockIdx.y * TN;

    float acc[4][4][4];
    #pragma unroll
    for (int m = 0; m < 4; m++)
        #pragma unroll
        for (int n = 0; n < 4; n++)
            #pragma unroll
            for (int r = 0; r < 4; r++) acc[m][n][r] = 0.f;

    // per-thread gmem assignment: 4 float4 of A, 4 of B per chunk
    // f = i*256 + tid ; row = f>>3 ; k = (f&7)*4
    float4 ra[4], rb[4];
    {
        #pragma unroll
        for (int i = 0; i < 4; i++) {
            int f = i * 256 + tid;
            int row = f >> 3, k = (f & 7) * 4;
            ra[i] = *(const float4*)(A + (size_t)(tileM + row) * DIM + k);
            rb[i] = *(const float4*)(B + (size_t)(tileN + row) * DIM + k);
        }
    }

    for (int ch = 0; ch < NCHUNK; ++ch) {
        const int buf = ch & 1;
        uint32_t* aw  = smw + buf * BUF_WORDS;                 // A hi
        uint32_t* alw = aw + TILE_WORDS;                       // A lo
        uint32_t* bw  = alw + TILE_WORDS;                      // B hi
        uint32_t* blw = bw + TILE_WORDS;                       // B lo

        // convert staged regs -> smem (fragment-native permuted layout)
        #pragma unroll
        for (int i = 0; i < 4; i++) {
            int f = i * 256 + tid;
            int row = f >> 3, k = (f & 7) * 4;
            int k16 = k >> 4;
            int q = (k & 15) >> 1;                 // even
            int p0 = ((q & 3) * 2) + (q >> 2);
            int p1 = (((q + 1) & 3) * 2) + ((q + 1) >> 2);
            int base = (k16 * 128 + row) * 8;

            float4 v = ra[i];
            __nv_bfloat162 h0 = __floats2bfloat162_rn(v.x, v.y);
            float2 hf0 = __bfloat1622float2(h0);
            __nv_bfloat162 l0 = __floats2bfloat162_rn(v.x - hf0.x, v.y - hf0.y);
            __nv_bfloat162 h1 = __floats2bfloat162_rn(v.z, v.w);
            float2 hf1 = __bfloat1622float2(h1);
            __nv_bfloat162 l1 = __floats2bfloat162_rn(v.z - hf1.x, v.w - hf1.y);
            aw [base + p0] = *(uint32_t*)&h0;  aw [base + p1] = *(uint32_t*)&h1;
            alw[base + p0] = *(uint32_t*)&l0;  alw[base + p1] = *(uint32_t*)&l1;

            v = rb[i];
            h0 = __floats2bfloat162_rn(v.x, v.y);
            hf0 = __bfloat1622float2(h0);
            l0 = __floats2bfloat162_rn(v.x - hf0.x, v.y - hf0.y);
            h1 = __floats2bfloat162_rn(v.z, v.w);
            hf1 = __bfloat1622float2(h1);
            l1 = __floats2bfloat162_rn(v.z - hf1.x, v.w - hf1.y);
            bw [base + p0] = *(uint32_t*)&h0;  bw [base + p1] = *(uint32_t*)&h1;
            blw[base + p0] = *(uint32_t*)&l0;  blw[base + p1] = *(uint32_t*)&l1;
        }
        __syncthreads();

        // prefetch next chunk while computing this one
        if (ch + 1 < NCHUNK) {
            #pragma unroll
            for (int i = 0; i < 4; i++) {
                int f = i * 256 + tid;
                int row = f >> 3, k = (f & 7) * 4 + (ch + 1) * KC;
                ra[i] = *(const float4*)(A + (size_t)(tileM + row) * DIM + k);
                rb[i] = *(const float4*)(B + (size_t)(tileN + row) * DIM + k);
            }
        }

        // 3 passes: hi*hi, hi*lo, lo*hi
        #pragma unroll
        for (int t = 0; t < 3; t++) {
            const uint32_t* As = (t == 2) ? alw : aw;
            const uint32_t* Bs = (t == 1) ? blw : bw;
            #pragma unroll
            for (int s = 0; s < 2; s++) {
                uint32_t afr[4][4];
                #pragma unroll
                for (int m = 0; m < 4; m++) {
                    int row = wm * 64 + m * 16 + gID;
                    uint2 v0 = *(const uint2*)(As + (s * 128 + row) * 8 + tig * 2);
                    uint2 v1 = *(const uint2*)(As + (s * 128 + row + 8) * 8 + tig * 2);
                    afr[m][0] = v0.x; afr[m][2] = v0.y;
                    afr[m][1] = v1.x; afr[m][3] = v1.y;
                }
                uint32_t bfr[4][2];
                #pragma unroll
                for (int n = 0; n < 4; n++) {
                    int rowb = wn * 32 + n * 8 + gID;
                    uint2 v = *(const uint2*)(Bs + (s * 128 + rowb) * 8 + tig * 2);
                    bfr[n][0] = v.x; bfr[n][1] = v.y;
                }
                #pragma unroll
                for (int m = 0; m < 4; m++)
                    #pragma unroll
                    for (int n = 0; n < 4; n++)
                        mma16816(acc[m][n], afr[m], bfr[n]);
            }
        }
        __syncthreads();
    }

    // epilogue: write fragments to g_sim
    #pragma unroll
    for (int m = 0; m < 4; m++) {
        int row = tileM + wm * 64 + m * 16 + gID;
        #pragma unroll
        for (int n = 0; n < 4; n++) {
            int col = tileN + wn * 32 + n * 8 + tig * 2;
            *(float2*)(g_sim + (size_t)row * KQ + col) =
                make_float2(acc[m][n][0], acc[m][n][1]);
            *(float2*)(g_sim + (size_t)(row + 8) * KQ + col) =
                make_float2(acc[m][n][2], acc[m][n][3]);
        }
    }
}

// ---------------- kernel 2: per-query top-200 + weighted vote + argmax ----------------
#define NBINS    16384
#define CAND_MAX 1024
#define TOPK_SMEM (NBINS*4 + 1024*4 + CAND_MAX*4 + CAND_MAX*4)

__global__ void __launch_bounds__(256)
topk_kernel(const int* __restrict__ qlabels, const int* __restrict__ labels) {
    extern __shared__ char smem[];
    unsigned* hist   = (unsigned*)smem;
    float*    scores = (float*)(smem + NBINS * 4);
    float*    cval   = scores + 1024;
    int*      clab   = (int*)(cval + CAND_MAX);

    __shared__ unsigned s_gsum[256];
    __shared__ int s_B, s_cGreater, s_cnt;
    __shared__ float s_bv[256];
    __shared__ int   s_bi[256];

    const int tid = threadIdx.x;
    const int q   = blockIdx.x;
    const float* row = g_sim + (size_t)q * KQ;

    for (int i = tid; i < NBINS; i += 256) hist[i] = 0u;
    for (int i = tid; i < 1024;  i += 256) scores[i] = 0.f;
    if (tid == 0) s_cnt = 0;
    __syncthreads();

    for (int i = tid; i < KQ; i += 256) {
        unsigned u = orderf(row[i]);
        atomicAdd(&hist[u >> 18], 1u);
    }
    __syncthreads();

    unsigned gs = 0;
    #pragma unroll 8
    for (int b = 0; b < 64; b++) gs += hist[tid * 64 + b];
    s_gsum[tid] = gs;
    __syncthreads();

    if (tid == 0) {
        unsigned cum = 0; int B = 0; unsigned cG = 0;
        for (int g = 255; g >= 0; --g) {
            if (cum + s_gsum[g] >= KNN) {
                for (int b = g * 64 + 63; b >= g * 64; --b) {
                    if (cum + hist[b] >= KNN) { B = b; cG = cum; break; }
                    cum += hist[b];
                }
                break;
            }
            cum += s_gsum[g];
        }
        s_B = B; s_cGreater = (int)cG;
    }
    __syncthreads();

    const int B = s_B;
    int need = KNN - s_cGreater;

    for (int i = tid; i < KQ; i += 256) {
        float v = row[i];
        int bin = (int)(orderf(v) >> 18);
        if (bin > B) {
            atomicAdd(&scores[qlabels[i]], expf(v * INVT));
        } else if (bin == B) {
            int p = atomicAdd(&s_cnt, 1);
            if (p < CAND_MAX) { cval[p] = v; clab[p] = qlabels[i]; }
        }
    }
    __syncthreads();

    int cnt = min(s_cnt, CAND_MAX);
    if (need > cnt) need = cnt;

    for (int i = tid; i < cnt; i += 256) {
        float v = cval[i];
        int rank = 0;
        for (int j = 0; j < cnt; j++) {
            float w = cval[j];
            rank += (w > v) || (w == v && j < i);
        }
        if (rank < need) atomicAdd(&scores[clab[i]], expf(v * INVT));
    }
    __syncthreads();

    float best = -1.f; int bi = NCLS;
    for (int c = tid; c < NCLS; c += 256) {
        float v = scores[c];
        if (v > best) { best = v; bi = c; }
    }
    s_bv[tid] = best; s_bi[tid] = bi;
    __syncthreads();
    for (int s = 128; s > 0; s >>= 1) {
        if (tid < s) {
            float ov = s_bv[tid + s]; int oi = s_bi[tid + s];
            if (ov > s_bv[tid] || (ov == s_bv[tid] && oi < s_bi[tid])) {
                s_bv[tid] = ov; s_bi[tid] = oi;
            }
        }
        __syncthreads();
    }
    if (tid == 0 && s_bi[0] == labels[q]) atomicAdd(&g_correct, 1);
}

// ---------------- kernel 3: queue update copy ----------------
__global__ void __launch_bounds__(256)
copy_kernel(const float* __restrict__ feats, const int* __restrict__ labels,
            const float* __restrict__ qf, const int* __restrict__ ql,
            const int* __restrict__ qptr, float* __restrict__ out) {
    const int ptr = qptr[0];
    size_t i4 = (size_t)blockIdx.x * 256 + threadIdx.x;
    if (i4 < (size_t)(NF / 4)) {
        int r = (int)(i4 >> 6);
        int rel = r - ptr; if (rel < 0) rel += KQ;
        float4 v = (rel < NQ) ? ((const float4*)feats)[(size_t)rel * 64 + (i4 & 63)]
                              : ((const float4*)qf)[i4];
        float* o = out + OUT_FEAT_OFF + i4 * 4;
        o[0] = v.x; o[1] = v.y; o[2] = v.z; o[3] = v.w;
    } else if (i4 < (size_t)(NF / 4 + NL / 4)) {
        int j4 = (int)(i4 - NF / 4);
        int4 lv = ((const int4*)ql)[j4];
        int base = j4 * 4;
        float* o = out + OUT_LAB_OFF + base;
        #pragma unroll
        for (int k = 0; k < 4; k++) {
            int i = base + k;
            int rel = i - ptr; if (rel < 0) rel += KQ;
            int lab = (rel < NQ) ? labels[rel] : ((const int*)&lv)[k];
            o[k] = (float)lab;
        }
    }
}

// ---------------- kernel 4: scalars ----------------
__global__ void finalize_kernel(const int* __restrict__ qptr, float* __restrict__ out) {
    out[0] = (float)g_correct * (1.0f / (float)NQ);
    out[OUT_PTR_OFF] = (float)((qptr[0] + NQ) % KQ);
}

// ---------------- launch ----------------
extern "C" void kernel_launch(void* const* d_in, const int* in_sizes, int n_in,
                              void* d_out, int out_size) {
    const float* feats  = (const float*)d_in[0];
    const int*   labels = (const int*)d_in[1];
    const float* qf     = (const float*)d_in[2];
    const int*   ql     = (const int*)d_in[3];
    const int*   qptr   = (const int*)d_in[4];
    float* out = (float*)d_out;

    cudaFuncSetAttribute(gemm_tc_kernel, cudaFuncAttributeMaxDynamicSharedMemorySize, GEMM_SMEM);
    cudaFuncSetAttribute(topk_kernel, cudaFuncAttributeMaxDynamicSharedMemorySize, TOPK_SMEM);

    zero_kernel<<<1, 1>>>();
    gemm_tc_kernel<<<dim3(NQ / TM, KQ / TN), 256, GEMM_SMEM>>>(feats, qf);
    topk_kernel<<<NQ, 256, TOPK_SMEM>>>(ql, labels);

    int total4 = NF / 4 + NL / 4;
    copy_kernel<<<(total4 + 255) / 256, 256>>>(feats, labels, qf, ql, qptr, out);
    finalize_kernel<<<1, 1>>>(qptr, out);
    (void)in_sizes; (void)n_in; (void)out_size;
}